// round 6
// baseline (speedup 1.0000x reference)
#include <cuda_runtime.h>

// TSM for fixed shape x=[8,16,96,112,112] fp32, k=4, elements=3.
//   c%3==0: out[t] = (t < 12) ? 0 : x[t]
//   c%3==1: out[t] = (t <  4) ? 0 : x[t-4]
//   c%3==2: out[t] = x[t]
// Plane (b,t,c) = 12544 floats = 3136 float4. Work unit = HALF plane:
// 224 threads x 7 float4 (uniform branch, MLP=7, single load batch).
// __launch_bounds__(224, 9) caps regs at 32 -> 9 blocks/SM = 2016 threads
// (98.4% theoretical occ). Normal (non-persistent) launch keeps block
// dispatch in address order for DRAM page locality (R3 lesson).

static constexpr int B = 8;
static constexpr int T = 16;
static constexpr int C = 96;
static constexpr int HW = 112 * 112;          // 12544
static constexpr int VEC_PER_PLANE = HW / 4;  // 3136
static constexpr int K_SHIFT = 4;
static constexpr int PLANES = B * T * C;      // 12288
static constexpr int THREADS = 224;
static constexpr int VPT = 7;                 // 224*7 = 1568 = plane/2
static constexpr int HALF_VEC = THREADS * VPT;
static constexpr int SHIFT_VEC = K_SHIFT * C * VEC_PER_PLANE;  // 1204224

__global__ __launch_bounds__(THREADS, 9)
void tsm_kernel(const float4* __restrict__ x, float4* __restrict__ out) {
    const int blk   = blockIdx.x;
    const int plane = blk >> 1;
    const int half  = blk & 1;

    const int c = plane % C;
    const int t = (plane / C) % T;
    const int m = c % 3;

    // Total vecs = 38,535,168 < 2^31: 32-bit indexing is safe.
    const int base = plane * VEC_PER_PLANE + half * HALF_VEC + (int)threadIdx.x;
    float4* __restrict__ o = out + base;

    const bool zero = (m == 0 && t < T - K_SHIFT) || (m == 1 && t < K_SHIFT);

    if (zero) {
        const float4 z = make_float4(0.f, 0.f, 0.f, 0.f);
        #pragma unroll
        for (int i = 0; i < VPT; i++)
            __stcs(&o[i * THREADS], z);
    } else {
        const float4* __restrict__ src = x + (base - (m == 1 ? SHIFT_VEC : 0));
        float4 v[VPT];
        #pragma unroll
        for (int i = 0; i < VPT; i++)
            v[i] = __ldcs(&src[i * THREADS]);
        #pragma unroll
        for (int i = 0; i < VPT; i++)
            __stcs(&o[i * THREADS], v[i]);
    }
}

extern "C" void kernel_launch(void* const* d_in, const int* in_sizes, int n_in,
                              void* d_out, int out_size) {
    const float4* x = (const float4*)d_in[0];
    float4* out = (float4*)d_out;
    tsm_kernel<<<PLANES * 2, THREADS>>>(x, out);
}

// round 7
// speedup vs baseline: 1.0175x; 1.0175x over previous
#include <cuda_runtime.h>

// TSM for fixed shape x=[8,16,96,112,112] fp32, k=4, elements=3.
//   c%3==0: out[t] = (t < 12) ? 0 : x[t]
//   c%3==1: out[t] = (t <  4) ? 0 : x[t-4]
//   c%3==2: out[t] = x[t]
// One block per (b,t,c) plane: 224 threads x 14 float4 = 3136 vecs,
// processed as two batches of 7 (MLP=7 per batch; batch-2 loads overlap
// batch-1 store drain). No launch_bounds cap: natural ~40 regs -> 7 CTAs/SM,
// the moderate-residency / deep-MLP regime that measured best (R2).
// Non-persistent launch keeps dispatch in address order (R3 lesson).

static constexpr int B = 8;
static constexpr int T = 16;
static constexpr int C = 96;
static constexpr int HW = 112 * 112;          // 12544
static constexpr int VEC_PER_PLANE = HW / 4;  // 3136
static constexpr int K_SHIFT = 4;
static constexpr int PLANES = B * T * C;      // 12288
static constexpr int THREADS = 224;
static constexpr int VPT = 7;                 // per batch; 2 batches = 14
static constexpr int HALF_VEC = THREADS * VPT;  // 1568

__global__ __launch_bounds__(THREADS)
void tsm_kernel(const float4* __restrict__ x, float4* __restrict__ out) {
    const int plane = blockIdx.x;
    const int c = plane % C;
    const int t = (plane / C) % T;
    const int m = c % 3;

    const long long base = (long long)plane * VEC_PER_PLANE + threadIdx.x;
    float4* __restrict__ o = out + base;

    const bool zero = (m == 0 && t < T - K_SHIFT) || (m == 1 && t < K_SHIFT);

    if (zero) {
        const float4 z = make_float4(0.f, 0.f, 0.f, 0.f);
        #pragma unroll
        for (int i = 0; i < 2 * VPT; i++)
            __stcs(&o[i * THREADS], z);
    } else {
        const float4* __restrict__ src = x + base
            - (m == 1 ? (long long)K_SHIFT * C * VEC_PER_PLANE : 0LL);

        float4 v[VPT];
        #pragma unroll
        for (int i = 0; i < VPT; i++)
            v[i] = __ldcs(&src[i * THREADS]);
        #pragma unroll
        for (int i = 0; i < VPT; i++)
            __stcs(&o[i * THREADS], v[i]);

        float4 w[VPT];
        #pragma unroll
        for (int i = 0; i < VPT; i++)
            w[i] = __ldcs(&src[HALF_VEC + i * THREADS]);
        #pragma unroll
        for (int i = 0; i < VPT; i++)
            __stcs(&o[HALF_VEC + i * THREADS], w[i]);
    }
}

extern "C" void kernel_launch(void* const* d_in, const int* in_sizes, int n_in,
                              void* d_out, int out_size) {
    const float4* x = (const float4*)d_in[0];
    float4* out = (float4*)d_out;
    tsm_kernel<<<PLANES, THREADS>>>(x, out);
}